// round 10
// baseline (speedup 1.0000x reference)
#include <cuda_runtime.h>
#include <cuda_fp16.h>
#include <cstdint>
#include <cstddef>

// out[b,s,d] = 16*sum_v x[b,s,v]*emb[v,d] + pos[s,d]*any(x[b,s,:])
// GEMM M=8192, N=256, K=8192. fp16 table = fp16(emb*16), x exact in fp16,
// fp32 accumulate. Baseline PTX path (compute_103: no tcgen05).
// R10: CUTLASS-shape CTA 128x256, 8 warps, warp 64x64 (halves LDSM traffic),
// split-K=2 via fp32 partials + combine kernel.

static constexpr int DIM_S = 1024;
static constexpr int DIM_V = 8192;
static constexpr int DIM_D = 256;

static constexpr int TM   = 128;            // CTA M tile
static constexpr int TKB  = 64;             // K per stage
static constexpr int NSTL = 64;             // stages per CTA (split-K=2)
static constexpr int RING = 4;

static constexpr uint32_t A_BYTES  = TM * TKB * 2;        // 16 KB
static constexpr uint32_t B_BYTES  = DIM_D * TKB * 2;     // 32 KB
static constexpr uint32_t ST_BYTES = A_BYTES + B_BYTES;   // 48 KB
static constexpr uint32_t SMEM_DYN = RING * ST_BYTES + 1024;  // ~193 KB

static constexpr size_t PART = (size_t)8192 * 256;

// fp16 transposed table [d][v] = fp16(emb[v][d]*16): 4 MB
__device__ __align__(128) unsigned short g_embT[(size_t)DIM_D * DIM_V];
// split-K partials + per-half any_tok flags
__device__ float g_part[2 * PART];          // 16 MB scratch
__device__ int   g_flags[2][8192];

__device__ __forceinline__ uint32_t smem_u32(const void* p) {
    return (uint32_t)__cvta_generic_to_shared(p);
}
__device__ __forceinline__ uint32_t sw128(uint32_t off) {
    return off ^ ((off >> 3) & 0x70u);
}

// ---------------------------------------------------------------------------
// Prep: transpose + fp16(emb*16)
// ---------------------------------------------------------------------------
__global__ void prep_transpose(const float* __restrict__ emb) {
    __shared__ float tile[32][33];
    const int v0 = blockIdx.x * 32, d0 = blockIdx.y * 32, t = threadIdx.x;
#pragma unroll
    for (int it = 0; it < 4; ++it) {
        int idx = t + it * 256, i = idx >> 5, j = idx & 31;
        tile[i][j] = emb[(size_t)(v0 + i) * DIM_D + d0 + j];
    }
    __syncthreads();
#pragma unroll
    for (int it = 0; it < 2; ++it) {
        int idx = t + it * 256, dl = idx >> 4, vp = idx & 15;
        __half2 h = __floats2half2_rn(tile[vp * 2][dl] * 16.0f,
                                      tile[vp * 2 + 1][dl] * 16.0f);
        *reinterpret_cast<__half2*>(
            &g_embT[(size_t)(d0 + dl) * DIM_V + v0 + vp * 2]) = h;
    }
}

// ---------------------------------------------------------------------------
// Producers (256 threads). Stage = 64 K-cols.
// A: 128 rows x 64 int32 -> fp16; each thread one half-row (32 ints).
// ---------------------------------------------------------------------------
__device__ __forceinline__ void load_a(int4* va, const int* __restrict__ x,
                                       int m0, int gstage, int t) {
    const int4* xr = reinterpret_cast<const int4*>(x);
    int row = t >> 1, q = t & 1;
    size_t o = (size_t)(m0 + row) * (DIM_V / 4) + (size_t)gstage * 16 + q * 8;
#pragma unroll
    for (int j = 0; j < 8; ++j) va[j] = xr[o + j];
}

__device__ __forceinline__ void store_a(const int4* va, uint32_t abase,
                                        int t, int* flags) {
    int row = t >> 1, q = t & 1;
    int any = 0;
#pragma unroll
    for (int s = 0; s < 4; ++s) {
        uint32_t pk[4];
#pragma unroll
        for (int h = 0; h < 2; ++h) {
            int4 v = va[s * 2 + h];
            any |= v.x | v.y | v.z | v.w;
            __half2 h0 = __floats2half2_rn((float)v.x, (float)v.y);
            __half2 h1 = __floats2half2_rn((float)v.z, (float)v.w);
            pk[h * 2 + 0] = *reinterpret_cast<uint32_t*>(&h0);
            pk[h * 2 + 1] = *reinterpret_cast<uint32_t*>(&h1);
        }
        uint32_t dst = abase + sw128((uint32_t)row * 128u +
                                     (uint32_t)q * 64u + (uint32_t)s * 16u);
        asm volatile("st.shared.v4.b32 [%0], {%1,%2,%3,%4};"
                     :: "r"(dst), "r"(pk[0]), "r"(pk[1]), "r"(pk[2]), "r"(pk[3]));
    }
    if (any) flags[row] = 1;                 // benign same-value race
}

__device__ __forceinline__ void issue_b(uint32_t bbase, int gstage, int t) {
    const char* bsrc = reinterpret_cast<const char*>(g_embT);
#pragma unroll
    for (int i = 0; i < 8; ++i) {
        int idx = t + i * 256;
        int row = idx >> 3, seg = idx & 7;   // 256 rows x 8 x 16B
        uint32_t dst = bbase + sw128((uint32_t)row * 128u + (uint32_t)seg * 16u);
        const void* src = bsrc + (size_t)row * (DIM_V * 2)
                               + (size_t)gstage * 128 + seg * 16;
        asm volatile("cp.async.cg.shared.global [%0], [%1], 16;"
                     :: "r"(dst), "l"(src));
    }
}

// ---------------------------------------------------------------------------
// GEMM: grid 128 = 64 M-tiles x 2 K-halves; 256 thr; 8 warps 2Mx4N; warp 64x64.
// ---------------------------------------------------------------------------
__global__ __launch_bounds__(256, 1)
void multihot_gemm(const int* __restrict__ x) {
    extern __shared__ char dynsm[];
    __shared__ int flags[TM];

    const int t = threadIdx.x;
    const int wid = t >> 5, lane = t & 31;
    const int wm = wid & 1, wn = wid >> 1;   // wm 0..1 (M), wn 0..3 (N)
    const int bm = blockIdx.x & 63, kh = blockIdx.x >> 6;
    const int m0 = bm * TM;
    const int gs0 = kh * NSTL;               // global stage base

    const uint32_t base = (smem_u32(dynsm) + 1023u) & ~1023u;

    for (int i = t; i < TM; i += 256) flags[i] = 0;
    __syncthreads();

    float acc[4][8][4];
#pragma unroll
    for (int a = 0; a < 4; ++a)
#pragma unroll
        for (int b = 0; b < 8; ++b)
#pragma unroll
            for (int c = 0; c < 4; ++c) acc[a][b][c] = 0.0f;

    // prologue: local stages 0..2
    int4 va[8];
    load_a(va, x, m0, gs0, t);
#pragma unroll
    for (int s = 0; s < RING - 1; ++s) {
        uint32_t sb = base + (uint32_t)s * ST_BYTES;
        store_a(va, sb, t, flags);
        issue_b(sb + A_BYTES, gs0 + s, t);
        asm volatile("cp.async.commit_group;" ::: "memory");
        load_a(va, x, m0, gs0 + s + 1, t);
    }

    // ldmatrix addresses (128B rows; swizzle xor = (lane&7)<<4)
    const uint32_t rxor    = (uint32_t)(lane & 7) << 4;
    const uint32_t a_khalf = (uint32_t)(lane >> 4) << 4;
    uint32_t a_row[4];
#pragma unroll
    for (int mt = 0; mt < 4; ++mt)
        a_row[mt] = (uint32_t)(wm * 64 + mt * 16 + (lane & 15)) * 128u;

    const uint32_t b_khalf = (uint32_t)((lane >> 3) & 1) << 4;
    uint32_t b_row[4];
#pragma unroll
    for (int ntp = 0; ntp < 4; ++ntp) {
        int nrow = wn * 64 + ntp * 16 + (lane & 7) + ((lane >> 4) << 3);
        b_row[ntp] = (uint32_t)nrow * 128u;
    }

#define LOAD_FRAGS(AF, BF, AB, BB, KS)                                         \
    do {                                                                       \
        const uint32_t kb = (uint32_t)(KS) * 32u;                              \
        _Pragma("unroll")                                                      \
        for (int mt = 0; mt < 4; ++mt) {                                       \
            uint32_t addr = (AB) + a_row[mt] + ((kb + a_khalf) ^ rxor);        \
            asm volatile("ldmatrix.sync.aligned.m8n8.x4.shared.b16 "           \
                         "{%0,%1,%2,%3}, [%4];"                                \
                         : "=r"((AF)[mt][0]), "=r"((AF)[mt][1]),               \
                           "=r"((AF)[mt][2]), "=r"((AF)[mt][3])                \
                         : "r"(addr));                                         \
        }                                                                      \
        _Pragma("unroll")                                                      \
        for (int ntp = 0; ntp < 4; ++ntp) {                                    \
            uint32_t addr = (BB) + b_row[ntp] + ((kb + b_khalf) ^ rxor);       \
            asm volatile("ldmatrix.sync.aligned.m8n8.x4.shared.b16 "           \
                         "{%0,%1,%2,%3}, [%4];"                                \
                         : "=r"((BF)[ntp][0]), "=r"((BF)[ntp][1]),             \
                           "=r"((BF)[ntp][2]), "=r"((BF)[ntp][3])              \
                         : "r"(addr));                                         \
        }                                                                      \
    } while (0)

#define MMA_SET(AF, BF)                                                        \
    do {                                                                       \
        _Pragma("unroll")                                                      \
        for (int mt = 0; mt < 4; ++mt) {                                       \
            _Pragma("unroll")                                                  \
            for (int nt = 0; nt < 8; ++nt) {                                   \
                float* c = acc[mt][nt];                                        \
                const uint32_t* bp = &(BF)[nt >> 1][(nt & 1) * 2];             \
                asm("mma.sync.aligned.m16n8k16.row.col.f32.f16.f16.f32 "       \
                    "{%0,%1,%2,%3}, {%4,%5,%6,%7}, {%8,%9}, {%0,%1,%2,%3};"    \
                    : "+f"(c[0]), "+f"(c[1]), "+f"(c[2]), "+f"(c[3])           \
                    : "r"((AF)[mt][0]), "r"((AF)[mt][1]),                      \
                      "r"((AF)[mt][2]), "r"((AF)[mt][3]),                      \
                      "r"(bp[0]), "r"(bp[1]));                                 \
            }                                                                  \
        }                                                                      \
    } while (0)

    uint32_t af0[4][4], bf0[4][4], af1[4][4], bf1[4][4];

    // mainloop (local stages)
#pragma unroll 1
    for (int k = 0; k < NSTL; ++k) {
        asm volatile("cp.async.wait_group %0;" :: "n"(RING - 2) : "memory");
        __syncthreads();

        const uint32_t soff = (uint32_t)(k & (RING - 1)) * ST_BYTES;
        const uint32_t ab = base + soff;
        const uint32_t bb = base + soff + A_BYTES;

        LOAD_FRAGS(af0, bf0, ab, bb, 0);     // early: overlaps producer

        if (k + RING - 1 < NSTL) {
            uint32_t sb = base + (uint32_t)((k + RING - 1) & (RING - 1)) * ST_BYTES;
            store_a(va, sb, t, flags);
            issue_b(sb + A_BYTES, gs0 + k + RING - 1, t);
        }
        if (k + RING < NSTL) load_a(va, x, m0, gs0 + k + RING, t);
        asm volatile("cp.async.commit_group;" ::: "memory");

        LOAD_FRAGS(af1, bf1, ab, bb, 1);
        MMA_SET(af0, bf0);
        LOAD_FRAGS(af0, bf0, ab, bb, 2);
        MMA_SET(af1, bf1);
        LOAD_FRAGS(af1, bf1, ab, bb, 3);
        MMA_SET(af0, bf0);
        MMA_SET(af1, bf1);
    }

    __syncthreads();   // flags fully written

    // epilogue: write fp32 partials + per-half flags
    float* part = g_part + (size_t)kh * PART;
#pragma unroll
    for (int mt = 0; mt < 4; ++mt) {
#pragma unroll
        for (int half = 0; half < 2; ++half) {
            const int rl = wm * 64 + mt * 16 + (lane >> 2) + half * 8;
            const int grow = m0 + rl;
            float* prow = part + (size_t)grow * DIM_D;
            if (wn == 0 && (lane & 3) == 0)
                g_flags[kh][grow] = flags[rl];
#pragma unroll
            for (int nt = 0; nt < 8; ++nt) {
                const int col = wn * 64 + nt * 8 + (lane & 3) * 2;
                float2 ov;
                ov.x = acc[mt][nt][half * 2 + 0];
                ov.y = acc[mt][nt][half * 2 + 1];
                *reinterpret_cast<float2*>(prow + col) = ov;
            }
        }
    }
}

// ---------------------------------------------------------------------------
// Combine: out = p0 + p1 + pos * any_tok
// ---------------------------------------------------------------------------
__global__ void combine_kernel(const float* __restrict__ pos,
                               float* __restrict__ out) {
    int idx = blockIdx.x * 256 + threadIdx.x;    // 524288 threads
    int m = idx >> 6, dq = (idx & 63) << 2;
    float tokf = (g_flags[0][m] | g_flags[1][m]) ? 1.0f : 0.0f;
    float4 p0 = *reinterpret_cast<const float4*>(&g_part[(size_t)m * DIM_D + dq]);
    float4 p1 = *reinterpret_cast<const float4*>(&g_part[PART + (size_t)m * DIM_D + dq]);
    float4 pe = *reinterpret_cast<const float4*>(
        &pos[(size_t)(m & (DIM_S - 1)) * DIM_D + dq]);
    float4 o;
    o.x = p0.x + p1.x + pe.x * tokf;
    o.y = p0.y + p1.y + pe.y * tokf;
    o.z = p0.z + p1.z + pe.z * tokf;
    o.w = p0.w + p1.w + pe.w * tokf;
    *reinterpret_cast<float4*>(&out[(size_t)m * DIM_D + dq]) = o;
}

// ---------------------------------------------------------------------------
extern "C" void kernel_launch(void* const* d_in, const int* in_sizes, int n_in,
                              void* d_out, int out_size) {
    (void)in_sizes; (void)n_in; (void)out_size;
    const int*   x   = (const int*)d_in[0];     // [8,1024,8192] int32 (0/1)
    const float* emb = (const float*)d_in[1];   // [8192,256] f32
    const float* pos = (const float*)d_in[2];   // [1,1024,256] f32
    float* out = (float*)d_out;                 // [8,1024,256] f32

    cudaFuncSetAttribute(multihot_gemm,
                         cudaFuncAttributeMaxDynamicSharedMemorySize, SMEM_DYN);

    prep_transpose<<<dim3(DIM_V / 32, DIM_D / 32), 256>>>(emb);
    multihot_gemm<<<128, 256, SMEM_DYN>>>(x);
    combine_kernel<<<2048, 256>>>(pos, out);
}

// round 11
// speedup vs baseline: 1.5246x; 1.5246x over previous
#include <cuda_runtime.h>
#include <cuda_fp16.h>
#include <cstdint>
#include <cstddef>

// out[b,s,d] = 16*sum_v x[b,s,v]*emb[v,d] + pos[s,d]*any(x[b,s,:])
// GEMM M=8192, N=256, K=8192. fp16 table = fp16(emb*16), x exact in fp16,
// fp32 accumulate. Baseline PTX path (compute_103: no tcgen05).
// R11: CTA 64x256, 8 warps (2Mx4N), warp 32x64 (acc=64 regs), RING=2,
// __launch_bounds__(256,2) -> 2 CTAs/SM; split-K=2 (grid 256, all resident).

static constexpr int DIM_S = 1024;
static constexpr int DIM_V = 8192;
static constexpr int DIM_D = 256;

static constexpr int TM   = 64;             // CTA M tile
static constexpr int TKB  = 64;             // K per stage
static constexpr int NSTL = 64;             // stages per CTA (split-K=2)
static constexpr int RING = 2;

static constexpr uint32_t A_BYTES  = TM * TKB * 2;        // 8 KB
static constexpr uint32_t B_BYTES  = DIM_D * TKB * 2;     // 32 KB
static constexpr uint32_t ST_BYTES = A_BYTES + B_BYTES;   // 40 KB
static constexpr uint32_t SMEM_DYN = RING * ST_BYTES + 1024;  // ~81 KB

static constexpr size_t PART = (size_t)8192 * 256;

// fp16 transposed table [d][v] = fp16(emb[v][d]*16): 4 MB
__device__ __align__(128) unsigned short g_embT[(size_t)DIM_D * DIM_V];
// split-K partials + per-half any_tok flags
__device__ float g_part[2 * PART];          // 16 MB scratch
__device__ int   g_flags[2][8192];

__device__ __forceinline__ uint32_t smem_u32(const void* p) {
    return (uint32_t)__cvta_generic_to_shared(p);
}
__device__ __forceinline__ uint32_t sw128(uint32_t off) {
    return off ^ ((off >> 3) & 0x70u);
}

// ---------------------------------------------------------------------------
// Prep: transpose + fp16(emb*16)
// ---------------------------------------------------------------------------
__global__ void prep_transpose(const float* __restrict__ emb) {
    __shared__ float tile[32][33];
    const int v0 = blockIdx.x * 32, d0 = blockIdx.y * 32, t = threadIdx.x;
#pragma unroll
    for (int it = 0; it < 4; ++it) {
        int idx = t + it * 256, i = idx >> 5, j = idx & 31;
        tile[i][j] = emb[(size_t)(v0 + i) * DIM_D + d0 + j];
    }
    __syncthreads();
#pragma unroll
    for (int it = 0; it < 2; ++it) {
        int idx = t + it * 256, dl = idx >> 4, vp = idx & 15;
        __half2 h = __floats2half2_rn(tile[vp * 2][dl] * 16.0f,
                                      tile[vp * 2 + 1][dl] * 16.0f);
        *reinterpret_cast<__half2*>(
            &g_embT[(size_t)(d0 + dl) * DIM_V + v0 + vp * 2]) = h;
    }
}

// ---------------------------------------------------------------------------
// A producer: each thread owns 16 ints of one row (row=t>>2, chunk q=t&3),
// converts to 8 packed-fp16 regs AT LOAD TIME (x in {0,1}: exact bit trick).
// ---------------------------------------------------------------------------
__device__ __forceinline__ void load_conv_a(uint32_t* vap, int& any,
                                            const int* __restrict__ x,
                                            int m0, int gstage, int t) {
    const int4* xr = reinterpret_cast<const int4*>(x);
    int row = t >> 2, q = t & 3;
    size_t o = (size_t)(m0 + row) * (DIM_V / 4) + (size_t)gstage * 16 + q * 4;
    any = 0;
#pragma unroll
    for (int j = 0; j < 4; ++j) {
        int4 v = xr[o + j];
        any |= v.x | v.y | v.z | v.w;
        vap[2 * j + 0] = (uint32_t)v.x * 0x3C00u + (uint32_t)v.y * 0x3C000000u;
        vap[2 * j + 1] = (uint32_t)v.z * 0x3C00u + (uint32_t)v.w * 0x3C000000u;
    }
}

__device__ __forceinline__ void store_a(const uint32_t* vap, int any,
                                        uint32_t abase, int t, int* flags) {
    int row = t >> 2, q = t & 3;
    if (any) flags[row] = 1;                 // benign same-value race
#pragma unroll
    for (int s = 0; s < 2; ++s) {
        uint32_t dst = abase + sw128((uint32_t)row * 128u +
                                     (uint32_t)q * 32u + (uint32_t)s * 16u);
        asm volatile("st.shared.v4.b32 [%0], {%1,%2,%3,%4};"
                     :: "r"(dst), "r"(vap[s * 4 + 0]), "r"(vap[s * 4 + 1]),
                        "r"(vap[s * 4 + 2]), "r"(vap[s * 4 + 3]));
    }
}

__device__ __forceinline__ void issue_b(uint32_t bbase, int gstage, int t) {
    const char* bsrc = reinterpret_cast<const char*>(g_embT);
#pragma unroll
    for (int i = 0; i < 8; ++i) {
        int idx = t + i * 256;
        int row = idx >> 3, seg = idx & 7;   // 256 rows x 8 x 16B
        uint32_t dst = bbase + sw128((uint32_t)row * 128u + (uint32_t)seg * 16u);
        const void* src = bsrc + (size_t)row * (DIM_V * 2)
                               + (size_t)gstage * 128 + seg * 16;
        asm volatile("cp.async.cg.shared.global [%0], [%1], 16;"
                     :: "r"(dst), "l"(src));
    }
}

// ---------------------------------------------------------------------------
// GEMM: grid 256 = 128 M-tiles x 2 K-halves; 256 thr; 8 warps 2Mx4N;
// warp 32x64; 2 CTAs/SM.
// ---------------------------------------------------------------------------
__global__ __launch_bounds__(256, 2)
void multihot_gemm(const int* __restrict__ x) {
    extern __shared__ char dynsm[];
    __shared__ int flags[TM];

    const int t = threadIdx.x;
    const int wid = t >> 5, lane = t & 31;
    const int wm = wid & 1, wn = wid >> 1;   // wm 0..1 (M), wn 0..3 (N)
    const int bm = blockIdx.x & 127, kh = blockIdx.x >> 7;
    const int m0 = bm * TM;
    const int gs0 = kh * NSTL;

    const uint32_t base = (smem_u32(dynsm) + 1023u) & ~1023u;

    for (int i = t; i < TM; i += 256) flags[i] = 0;
    __syncthreads();

    float acc[2][8][4];
#pragma unroll
    for (int a = 0; a < 2; ++a)
#pragma unroll
        for (int b = 0; b < 8; ++b)
#pragma unroll
            for (int c = 0; c < 4; ++c) acc[a][b][c] = 0.0f;

    // prologue: stage 0 produced, stage 1 prefetched to regs
    uint32_t vap[8];
    int any;
    load_conv_a(vap, any, x, m0, gs0, t);
    store_a(vap, any, base, t, flags);
    issue_b(base + A_BYTES, gs0, t);
    asm volatile("cp.async.commit_group;" ::: "memory");
    load_conv_a(vap, any, x, m0, gs0 + 1, t);

    // ldmatrix addresses (128B rows; swizzle xor = (lane&7)<<4)
    const uint32_t rxor    = (uint32_t)(lane & 7) << 4;
    const uint32_t a_khalf = (uint32_t)(lane >> 4) << 4;
    uint32_t a_row[2];
#pragma unroll
    for (int mt = 0; mt < 2; ++mt)
        a_row[mt] = (uint32_t)(wm * 32 + mt * 16 + (lane & 15)) * 128u;

    const uint32_t b_khalf = (uint32_t)((lane >> 3) & 1) << 4;
    uint32_t b_row[4];
#pragma unroll
    for (int ntp = 0; ntp < 4; ++ntp) {
        int nrow = wn * 64 + ntp * 16 + (lane & 7) + ((lane >> 4) << 3);
        b_row[ntp] = (uint32_t)nrow * 128u;
    }

#define LOAD_A_FRAG(AF, AB, KS)                                                \
    do {                                                                       \
        const uint32_t kb = (uint32_t)(KS) * 32u;                              \
        _Pragma("unroll")                                                      \
        for (int mt = 0; mt < 2; ++mt) {                                       \
            uint32_t addr = (AB) + a_row[mt] + ((kb + a_khalf) ^ rxor);        \
            asm volatile("ldmatrix.sync.aligned.m8n8.x4.shared.b16 "           \
                         "{%0,%1,%2,%3}, [%4];"                                \
                         : "=r"((AF)[mt][0]), "=r"((AF)[mt][1]),               \
                           "=r"((AF)[mt][2]), "=r"((AF)[mt][3])                \
                         : "r"(addr));                                         \
        }                                                                      \
    } while (0)

#define LOAD_B_FRAG(BF, BB, KS)                                                \
    do {                                                                       \
        const uint32_t kb = (uint32_t)(KS) * 32u;                              \
        _Pragma("unroll")                                                      \
        for (int ntp = 0; ntp < 4; ++ntp) {                                    \
            uint32_t addr = (BB) + b_row[ntp] + ((kb + b_khalf) ^ rxor);       \
            asm volatile("ldmatrix.sync.aligned.m8n8.x4.shared.b16 "           \
                         "{%0,%1,%2,%3}, [%4];"                                \
                         : "=r"((BF)[ntp][0]), "=r"((BF)[ntp][1]),             \
                           "=r"((BF)[ntp][2]), "=r"((BF)[ntp][3])              \
                         : "r"(addr));                                         \
        }                                                                      \
    } while (0)

#define MMA_SET(AF, BF)                                                        \
    do {                                                                       \
        _Pragma("unroll")                                                      \
        for (int mt = 0; mt < 2; ++mt) {                                       \
            _Pragma("unroll")                                                  \
            for (int nt = 0; nt < 8; ++nt) {                                   \
                float* c = acc[mt][nt];                                        \
                const uint32_t* bp = &(BF)[nt >> 1][(nt & 1) * 2];             \
                asm("mma.sync.aligned.m16n8k16.row.col.f32.f16.f16.f32 "       \
                    "{%0,%1,%2,%3}, {%4,%5,%6,%7}, {%8,%9}, {%0,%1,%2,%3};"    \
                    : "+f"(c[0]), "+f"(c[1]), "+f"(c[2]), "+f"(c[3])           \
                    : "r"((AF)[mt][0]), "r"((AF)[mt][1]),                      \
                      "r"((AF)[mt][2]), "r"((AF)[mt][3]),                      \
                      "r"(bp[0]), "r"(bp[1]));                                 \
            }                                                                  \
        }                                                                      \
    } while (0)

    uint32_t af0[2][4], af1[2][4], bf[4][4];

    // mainloop
#pragma unroll 1
    for (int k = 0; k < NSTL; ++k) {
        asm volatile("cp.async.wait_group 0;" ::: "memory");
        __syncthreads();

        const uint32_t ab = base + (uint32_t)(k & 1) * ST_BYTES;
        const uint32_t bb = ab + A_BYTES;

        // slice-0 fragments early: LDSM latency overlaps producer work
        LOAD_A_FRAG(af0, ab, 0);
        LOAD_B_FRAG(bf, bb, 0);

        if (k + 1 < NSTL) {
            uint32_t sb = base + (uint32_t)((k + 1) & 1) * ST_BYTES;
            store_a(vap, any, sb, t, flags);
            issue_b(sb + A_BYTES, gs0 + k + 1, t);
        }
        asm volatile("cp.async.commit_group;" ::: "memory");
        if (k + 2 < NSTL) load_conv_a(vap, any, x, m0, gs0 + k + 2, t);

        // A double-buffered, B single-buffered (reg budget), MMA interleaved
        LOAD_A_FRAG(af1, ab, 1);
        MMA_SET(af0, bf);
        LOAD_B_FRAG(bf, bb, 1);
        LOAD_A_FRAG(af0, ab, 2);
        MMA_SET(af1, bf);
        LOAD_B_FRAG(bf, bb, 2);
        LOAD_A_FRAG(af1, ab, 3);
        MMA_SET(af0, bf);
        LOAD_B_FRAG(bf, bb, 3);
        MMA_SET(af1, bf);
    }

    __syncthreads();   // flags fully written

    // epilogue: fp32 partials + per-half flags
    float* part = g_part + (size_t)kh * PART;
#pragma unroll
    for (int mt = 0; mt < 2; ++mt) {
#pragma unroll
        for (int half = 0; half < 2; ++half) {
            const int rl = wm * 32 + mt * 16 + (lane >> 2) + half * 8;
            const int grow = m0 + rl;
            float* prow = part + (size_t)grow * DIM_D;
            if (wn == 0 && (lane & 3) == 0)
                g_flags[kh][grow] = flags[rl];
#pragma unroll
            for (int nt = 0; nt < 8; ++nt) {
                const int col = wn * 64 + nt * 8 + (lane & 3) * 2;
                float2 ov;
                ov.x = acc[mt][nt][half * 2 + 0];
                ov.y = acc[mt][nt][half * 2 + 1];
                *reinterpret_cast<float2*>(prow + col) = ov;
            }
        }
    }
}

// ---------------------------------------------------------------------------
// Combine: out = p0 + p1 + pos * any_tok
// ---------------------------------------------------------------------------
__global__ void combine_kernel(const float* __restrict__ pos,
                               float* __restrict__ out) {
    int idx = blockIdx.x * 256 + threadIdx.x;    // 524288 threads
    int m = idx >> 6, dq = (idx & 63) << 2;
    float tokf = (g_flags[0][m] | g_flags[1][m]) ? 1.0f : 0.0f;
    float4 p0 = *reinterpret_cast<const float4*>(&g_part[(size_t)m * DIM_D + dq]);
    float4 p1 = *reinterpret_cast<const float4*>(&g_part[PART + (size_t)m * DIM_D + dq]);
    float4 pe = *reinterpret_cast<const float4*>(
        &pos[(size_t)(m & (DIM_S - 1)) * DIM_D + dq]);
    float4 o;
    o.x = p0.x + p1.x + pe.x * tokf;
    o.y = p0.y + p1.y + pe.y * tokf;
    o.z = p0.z + p1.z + pe.z * tokf;
    o.w = p0.w + p1.w + pe.w * tokf;
    *reinterpret_cast<float4*>(&out[(size_t)m * DIM_D + dq]) = o;
}

// ---------------------------------------------------------------------------
extern "C" void kernel_launch(void* const* d_in, const int* in_sizes, int n_in,
                              void* d_out, int out_size) {
    (void)in_sizes; (void)n_in; (void)out_size;
    const int*   x   = (const int*)d_in[0];     // [8,1024,8192] int32 (0/1)
    const float* emb = (const float*)d_in[1];   // [8192,256] f32
    const float* pos = (const float*)d_in[2];   // [1,1024,256] f32
    float* out = (float*)d_out;                 // [8,1024,256] f32

    cudaFuncSetAttribute(multihot_gemm,
                         cudaFuncAttributeMaxDynamicSharedMemorySize, SMEM_DYN);

    prep_transpose<<<dim3(DIM_V / 32, DIM_D / 32), 256>>>(emb);
    multihot_gemm<<<256, 256, SMEM_DYN>>>(x);
    combine_kernel<<<2048, 256>>>(pos, out);
}